// round 9
// baseline (speedup 1.0000x reference)
#include <cuda_runtime.h>
#include <math.h>

#define N_PART 4096
__device__ float g_partial[N_PART];

__device__ __forceinline__ float pseudo_angle(float x, float y) {
    // Monotone surrogate for atan2(y,x), range [-2,2], same branch cut at +-pi.
    float t = __fdividef(y, fabsf(x) + fabsf(y));
    if (x >= 0.0f) return t;
    return (y >= 0.0f) ? (2.0f - t) : (-2.0f - t);
}

// float -> order-preserving uint32
__device__ __forceinline__ unsigned int float_to_ouint(float f) {
    unsigned int u = __float_as_uint(f);
    return (u & 0x80000000u) ? ~u : (u | 0x80000000u);
}

__global__ void __launch_bounds__(256) fpdiou_main_kernel(
        const float* __restrict__ pred,
        const float* __restrict__ targ,
        int n) {
    float acc = 0.0f;

    for (int i = blockIdx.x * blockDim.x + threadIdx.x; i < n;
         i += gridDim.x * blockDim.x) {

        // ---- load boxes ----
        float px = pred[5*i+0], py = pred[5*i+1], pw = pred[5*i+2], ph = pred[5*i+3], pa = pred[5*i+4];
        float tx = targ[5*i+0], ty = targ[5*i+1], tw = targ[5*i+2], th = targ[5*i+3], ta = targ[5*i+4];

        // ---- box2corners ----
        const float DXS[4] = {0.5f,-0.5f,-0.5f,0.5f};
        const float DYS[4] = {0.5f, 0.5f,-0.5f,-0.5f};
        float c1x[4], c1y[4], c2x[4], c2y[4];
        {
            float s, c;
            __sincosf(pa, &s, &c);
            #pragma unroll
            for (int k = 0; k < 4; k++) {
                float dx = DXS[k]*pw, dy = DYS[k]*ph;
                c1x[k] = dx*c - dy*s + px;
                c1y[k] = dx*s + dy*c + py;
            }
            __sincosf(ta, &s, &c);
            #pragma unroll
            for (int k = 0; k < 4; k++) {
                float dx = DXS[k]*tw, dy = DYS[k]*th;
                c2x[k] = dx*c - dy*s + tx;
                c2y[k] = dx*s + dy*c + ty;
            }
        }

        // ---- collect polygon vertices (reference order: c1, c2, inter[e1][e2]) ----
        float vx[24], vy[24];
        int kcnt = 0;

        // corners of box1 inside box2
        {
            float ax = c2x[0], ay = c2y[0];
            float abx = c2x[1]-ax, aby = c2y[1]-ay;
            float adx = c2x[3]-ax, ady = c2y[3]-ay;
            float iab = __fdividef(1.0f, abx*abx + aby*aby);
            float iad = __fdividef(1.0f, adx*adx + ady*ady);
            #pragma unroll
            for (int k = 0; k < 4; k++) {
                float amx = c1x[k]-ax, amy = c1y[k]-ay;
                float pab = (abx*amx + aby*amy)*iab;
                float pad = (adx*amx + ady*amy)*iad;
                const float e = 1e-6f;
                if (pab > -e && pab < 1.0f+e && pad > -e && pad < 1.0f+e) {
                    vx[kcnt] = c1x[k]; vy[kcnt] = c1y[k]; kcnt++;
                }
            }
        }
        // corners of box2 inside box1
        {
            float ax = c1x[0], ay = c1y[0];
            float abx = c1x[1]-ax, aby = c1y[1]-ay;
            float adx = c1x[3]-ax, ady = c1y[3]-ay;
            float iab = __fdividef(1.0f, abx*abx + aby*aby);
            float iad = __fdividef(1.0f, adx*adx + ady*ady);
            #pragma unroll
            for (int k = 0; k < 4; k++) {
                float amx = c2x[k]-ax, amy = c2y[k]-ay;
                float pab = (abx*amx + aby*amy)*iab;
                float pad = (adx*amx + ady*amy)*iad;
                const float e = 1e-6f;
                if (pab > -e && pab < 1.0f+e && pad > -e && pad < 1.0f+e) {
                    vx[kcnt] = c2x[k]; vy[kcnt] = c2y[k]; kcnt++;
                }
            }
        }
        // 4x4 edge-pair intersections
        #pragma unroll
        for (int e1 = 0; e1 < 4; e1++) {
            float x1 = c1x[e1], y1 = c1y[e1];
            float x2 = c1x[(e1+1)&3], y2 = c1y[(e1+1)&3];
            float ex = x2 - x1, ey = y2 - y1;
            #pragma unroll
            for (int e2 = 0; e2 < 4; e2++) {
                float x3 = c2x[e2], y3 = c2y[e2];
                float x4 = c2x[(e2+1)&3], y4 = c2y[(e2+1)&3];
                float fx = x4 - x3, fy = y4 - y3;
                float num   = fy*ex - fx*ey;
                float gx = x1 - x3, gy = y1 - y3;
                float den_t = fx*gy - fy*gx;
                float den_u = ex*gy - ey*gx;
                bool mask = false;
                if (num != 0.0f) {
                    float rnum = __fdividef(1.0f, num);
                    float t =  den_t * rnum;
                    float u = -den_u * rnum;
                    mask = (t > 0.0f) && (t < 1.0f) && (u > 0.0f) && (u < 1.0f);
                }
                if (mask) {
                    float t2 = __fdividef(den_t, num + 1e-8f);
                    vx[kcnt] = x1 + t2*ex;
                    vy[kcnt] = y1 + t2*ey;
                    kcnt++;
                }
            }
        }

        // ---- intersection area via angular sort + shoelace ----
        float inter = 0.0f;
        if (kcnt > 0) {
            float sx = 0.0f, sy = 0.0f;
            #pragma unroll 1
            for (int a = 0; a < kcnt; a++) { sx += vx[a]; sy += vy[a]; }
            float inv = __fdividef(1.0f, (float)kcnt);
            float mx = sx * inv, my = sy * inv;

            // packed sort key: [angle-as-ordered-uint truncated, 5 low bits = idx]
            // -> single-word insertion sort, stability built into the key
            //    (ties broken by original index == reference's stable argsort).
            unsigned int key[24];
            #pragma unroll 1
            for (int a = 0; a < kcnt; a++) {
                unsigned int u = float_to_ouint(pseudo_angle(vx[a]-mx, vy[a]-my));
                key[a] = (u & 0xFFFFFFE0u) | (unsigned int)a;
            }
            #pragma unroll 1
            for (int a = 1; a < kcnt; a++) {
                unsigned int kv = key[a];
                int b = a - 1;
                #pragma unroll 1
                while (b >= 0 && key[b] > kv) { key[b+1] = key[b]; b--; }
                key[b+1] = kv;
            }

            // shoelace over sorted order (gather by low-bits index)
            int j0 = key[0] & 31u;
            float fx0 = vx[j0], fy0 = vy[j0];
            float pxx = fx0, pyy = fy0;
            float area = 0.0f;
            #pragma unroll 1
            for (int a = 1; a < kcnt; a++) {
                int j = key[a] & 31u;
                float cx = vx[j], cy = vy[j];
                area += pxx*cy - pyy*cx;
                pxx = cx; pyy = cy;
            }
            area += pxx*fy0 - pyy*fx0;   // wrap-around edge
            inter = fabsf(area) * 0.5f;
        }

        // ---- IoU ----
        float area1 = pw * ph;
        float area2 = tw * th;
        float iou = __fdividef(inter, area1 + area2 - inter);
        iou = fmaxf(iou, 1e-6f);

        // ---- FPDIoU distance term: stable x-sort of 4 corners per box ----
        // Adjacent compare-exchange bubble network (strict >) == stable,
        // constant indices -> register-resident.
        float psx[4], psy[4], gsx[4], gsy[4];
        #pragma unroll
        for (int k = 0; k < 4; k++) { psx[k]=c1x[k]; psy[k]=c1y[k]; gsx[k]=c2x[k]; gsy[k]=c2y[k]; }

        #define CE(X, Y, A, B) { if (X[A] > X[B]) { float t_ = X[A]; X[A]=X[B]; X[B]=t_; \
                                                    t_ = Y[A]; Y[A]=Y[B]; Y[B]=t_; } }
        CE(psx, psy, 0, 1); CE(psx, psy, 1, 2); CE(psx, psy, 2, 3);
        CE(psx, psy, 0, 1); CE(psx, psy, 1, 2);
        CE(psx, psy, 0, 1);
        CE(gsx, gsy, 0, 1); CE(gsx, gsy, 1, 2); CE(gsx, gsy, 2, 3);
        CE(gsx, gsy, 0, 1); CE(gsx, gsy, 1, 2);
        CE(gsx, gsy, 0, 1);
        #undef CE

        float d0 = gsx[0] - psx[0];
        float d = 2.0f * d0 * d0;
        #pragma unroll
        for (int k = 1; k < 4; k++) {
            float ddx = psx[k] - gsx[k];
            float ddy = psy[k] - gsy[k];
            d += ddx*ddx + ddy*ddy;
        }
        float res = d * (1.0f / (4.0f * 1024.0f * 1024.0f));

        acc += 1.0f - iou + res;
    }

    // ---- block reduction: warp shuffle + one shared slot per warp ----
    #pragma unroll
    for (int off = 16; off > 0; off >>= 1)
        acc += __shfl_xor_sync(0xFFFFFFFFu, acc, off);

    __shared__ float swarp[8];
    int lane = threadIdx.x & 31;
    int wid  = threadIdx.x >> 5;
    if (lane == 0) swarp[wid] = acc;
    __syncthreads();
    if (wid == 0) {
        float v = (lane < 8) ? swarp[lane] : 0.0f;
        #pragma unroll
        for (int off = 4; off > 0; off >>= 1)
            v += __shfl_xor_sync(0xFFFFFFFFu, v, off);
        if (lane == 0) g_partial[blockIdx.x] = v;
    }
}

__global__ void fpdiou_reduce_kernel(float* __restrict__ out, int nblocks, float inv_n) {
    __shared__ double sbuf[512];
    int tid = threadIdx.x;
    double a = 0.0;
    for (int j = tid; j < nblocks; j += 512)
        a += (double)g_partial[j];
    sbuf[tid] = a;
    __syncthreads();
    #pragma unroll
    for (int off = 256; off > 0; off >>= 1) {
        if (tid < off) sbuf[tid] += sbuf[tid + off];
        __syncthreads();
    }
    if (tid == 0) out[0] = (float)(sbuf[0] * (double)inv_n);
}

extern "C" void kernel_launch(void* const* d_in, const int* in_sizes, int n_in,
                              void* d_out, int out_size) {
    const float* pred = (const float*)d_in[0];
    const float* targ = (const float*)d_in[1];
    float* out = (float*)d_out;
    int n = in_sizes[0] / 5;

    int threads = 256;
    int blocks = (n + threads - 1) / threads;
    if (blocks > N_PART) blocks = N_PART;   // grid-stride handles the rest
    fpdiou_main_kernel<<<blocks, threads>>>(pred, targ, n);
    fpdiou_reduce_kernel<<<1, 512>>>(out, blocks, 1.0f / (float)n);
}